// round 14
// baseline (speedup 1.0000x reference)
#include <cuda_runtime.h>
#include <cuda_bf16.h>
#include <cstdint>

#define NUM_VERTS 6890
#define NUM_FACES 13776
#define HH 1024
#define WW 1024
#define NB 16
#define HW (HH * WW)

// Element counts (pairwise distinct) used to identify inputs regardless of order.
#define SZ_VERTS  (16 * NUM_VERTS * 3)   // 330720  f32
#define SZ_FACES  (NUM_FACES * 3)        // 41328   idx
#define SZ_PIX    (HW)                   // 1048576 idx
#define SZ_BARY   (HW * 3)               // 3145728 f32

#define TILE_PX    1024                  // pixels per block (256 thr * 4 px)
#define TILE_BYTES (TILE_PX * 3 * 4)     // 12288 B per batch tile
#define BATCH_BYTES ((size_t)HW * 3 * 4) // 12 MiB per output batch

// Face-vertex attributes padded to 64 B/face so one pixel's three float4
// loads land in a single 128-B line. 13776 * 64 B = 882 KB, L2-resident.
__device__ float4 g_face_attr[NUM_FACES * 4];

// ---------------------------------------------------------------------------
// Per-block dtype probe (no separate launch). Reads the first 64 values of an
// index buffer as int64 — 512 B, safe under either dtype (smallest buffer is
// 41328*4 B). int32 data misread as int64 goes out of range immediately.
// ---------------------------------------------------------------------------
__device__ __forceinline__ bool probe_is_i64(const void* buf, long long lo,
                                             long long hi, int* s_bad) {
    if (threadIdx.x == 0) *s_bad = 0;
    __syncthreads();
    if (threadIdx.x < 64) {
        long long v = ((const long long*)buf)[threadIdx.x];
        if (v < lo || v >= hi) atomicOr(s_bad, 1);
    }
    __syncthreads();
    return (*s_bad == 0);
}

// ---------------------------------------------------------------------------
// Stage 1: collapse face->vertex indirection into the padded L2 table.
// Only batch 0 of verts_attr matters (reference's replicated indexing bug).
// ---------------------------------------------------------------------------
__global__ __launch_bounds__(256) void uvr_build_face_table(
        const float* __restrict__ verts,
        const void*  __restrict__ faces) {
    __shared__ int s_bad;
    bool i64 = probe_is_i64(faces, 0, NUM_VERTS, &s_bad);

    int i = blockIdx.x * blockDim.x + threadIdx.x;   // over F*3
    if (i >= NUM_FACES * 3) return;
    long long v = i64 ? ((const long long*)faces)[i]
                      : (long long)((const int*)faces)[i];
    int vi = (int)v;
    vi = (vi < 0) ? 0 : (vi >= NUM_VERTS ? NUM_VERTS - 1 : vi);  // safety clamp
    const float* p = verts + (size_t)vi * 3;
    int f = i / 3, k = i - f * 3;
    g_face_attr[f * 4 + k] = make_float4(p[0], p[1], p[2], 0.0f);
}

// ---------------------------------------------------------------------------
// Stage 2: interpolate into a 12 KB smem tile, then broadcast to all 16
// batches via cp.async.bulk (TMA path) — zero STG wavefronts through L1.
// Grid exactly covers HW: 1024 blocks * 256 threads * 4 px.
// ---------------------------------------------------------------------------
__global__ __launch_bounds__(256) void uvr_render(
        const void*  __restrict__ pixv,   // (H, W) indices
        const float* __restrict__ bary,   // (H, W, 3) f32
        float*       __restrict__ out) {  // (N, H, W, 3) f32
    __shared__ int s_bad;
    __shared__ __align__(128) float s_tile[TILE_PX * 3];   // 12 KB

    bool pix_i64 = probe_is_i64(pixv, -1, NUM_FACES, &s_bad);

    int t  = blockIdx.x * blockDim.x + threadIdx.x;
    int p0 = t * 4;                       // 4 pixels per thread

    long long pf[4];
    if (pix_i64) {
        longlong2 a = ((const longlong2*)pixv)[t * 2];
        longlong2 b = ((const longlong2*)pixv)[t * 2 + 1];
        pf[0] = a.x; pf[1] = a.y; pf[2] = b.x; pf[3] = b.y;
    } else {
        int4 a = ((const int4*)pixv)[t];
        pf[0] = a.x; pf[1] = a.y; pf[2] = a.z; pf[3] = a.w;
    }

    const float4* bv = reinterpret_cast<const float4*>(bary + (size_t)p0 * 3);
    float4 b0 = bv[0], b1 = bv[1], b2 = bv[2];
    float bc[4][3] = {
        {b0.x, b0.y, b0.z},
        {b0.w, b1.x, b1.y},
        {b1.z, b1.w, b2.x},
        {b2.y, b2.z, b2.w}
    };

    float r[4][3];
#pragma unroll
    for (int i = 0; i < 4; i++) {
        long long f = pf[i];
        float m = (f >= 0) ? 1.0f : 0.0f;
        int idx = (int)f;
        idx = (idx < 0) ? 0 : (idx >= NUM_FACES ? NUM_FACES - 1 : idx);  // clamp
        // One 128-B line per pixel (64-B padded record).
        float4 a0 = g_face_attr[idx * 4 + 0];
        float4 a1 = g_face_attr[idx * 4 + 1];
        float4 a2 = g_face_attr[idx * 4 + 2];
        r[i][0] = m * (bc[i][0] * a0.x + bc[i][1] * a1.x + bc[i][2] * a2.x);
        r[i][1] = m * (bc[i][0] * a0.y + bc[i][1] * a1.y + bc[i][2] * a2.y);
        r[i][2] = m * (bc[i][0] * a0.z + bc[i][1] * a1.z + bc[i][2] * a2.z);
    }

    // Pack 12 floats -> 3 float4 and stage in smem (48 contiguous bytes/thread).
    float4* sp = reinterpret_cast<float4*>(s_tile + threadIdx.x * 12);
    sp[0] = make_float4(r[0][0], r[0][1], r[0][2], r[1][0]);
    sp[1] = make_float4(r[1][1], r[1][2], r[2][0], r[2][1]);
    sp[2] = make_float4(r[2][2], r[3][0], r[3][1], r[3][2]);

    __syncthreads();

    if (threadIdx.x == 0) {
        // Make generic-proxy smem writes visible to the async (TMA) proxy.
        asm volatile("fence.proxy.async.shared::cta;" ::: "memory");
        uint32_t saddr;
        asm("{ .reg .u64 t; cvta.to.shared.u64 t, %1; cvt.u32.u64 %0, t; }"
            : "=r"(saddr) : "l"((const void*)s_tile));
        size_t tile_off = (size_t)blockIdx.x * TILE_BYTES;
#pragma unroll
        for (int n = 0; n < NB; n++) {
            char* dst = (char*)out + (size_t)n * BATCH_BYTES + tile_off;
            asm volatile(
                "cp.async.bulk.global.shared::cta.bulk_group [%0], [%1], %2;"
                :: "l"(dst), "r"(saddr), "r"((int)TILE_BYTES) : "memory");
        }
        asm volatile("cp.async.bulk.commit_group;" ::: "memory");
        // Drain before CTA exit (smem is the copy source).
        asm volatile("cp.async.bulk.wait_group 0;" ::: "memory");
    }
}

extern "C" void kernel_launch(void* const* d_in, const int* in_sizes, int n_in,
                              void* d_out, int out_size) {
    // Identify inputs by element count (pairwise distinct) — order-proof.
    const float* verts = nullptr;
    const void*  faces = nullptr;
    const void*  pix   = nullptr;
    const float* bary  = nullptr;
    for (int i = 0; i < n_in; i++) {
        switch (in_sizes[i]) {
            case SZ_VERTS: verts = (const float*)d_in[i]; break;
            case SZ_FACES: faces = d_in[i];               break;
            case SZ_PIX:   pix   = d_in[i];               break;
            case SZ_BARY:  bary  = (const float*)d_in[i]; break;
            default: break;
        }
    }
    if (!verts) verts = (const float*)d_in[0];
    if (!faces) faces = d_in[1];
    if (!pix)   pix   = d_in[2];
    if (!bary)  bary  = (const float*)d_in[3];

    float* out = (float*)d_out;
    (void)out_size;

    {
        int n = NUM_FACES * 3;
        uvr_build_face_table<<<(n + 255) / 256, 256>>>(verts, faces);
    }
    {
        uvr_render<<<HW / TILE_PX, 256>>>(pix, bary, out);   // 1024 blocks
    }
}

// round 15
// speedup vs baseline: 1.2684x; 1.2684x over previous
#include <cuda_runtime.h>
#include <cuda_bf16.h>

#define NUM_VERTS 6890
#define NUM_FACES 13776
#define HH 1024
#define WW 1024
#define NB 16
#define HW (HH * WW)

// Element counts (pairwise distinct) used to identify inputs regardless of order.
#define SZ_VERTS  (16 * NUM_VERTS * 3)   // 330720  f32
#define SZ_FACES  (NUM_FACES * 3)        // 41328   idx
#define SZ_PIX    (HW)                   // 1048576 idx
#define SZ_BARY   (HW * 3)               // 3145728 f32

#define BLK 128                          // threads per block
#define PXT 4                            // pixels per thread (float4-clean)
#define GRID (HW / (BLK * PXT))          // 2048 blocks -> ~1.15 waves @12 CTA/SM

// Face-vertex attributes padded to 64 B/face: one pixel's three float4 gather
// loads land in a single 128-B sector pair. 13776 * 64 B = 882 KB, L2-resident.
__device__ float4 g_face_attr[NUM_FACES * 4];

// ---------------------------------------------------------------------------
// Per-block dtype probe (no separate launch). Reads the first 64 values of an
// index buffer as int64 — 512 B, safe under either dtype (smallest buffer is
// 41328*4 B). int32 data misread as int64 goes out of range immediately.
// L2-broadcast after the first block touches it; cost ~hundreds of cycles.
// ---------------------------------------------------------------------------
__device__ __forceinline__ bool probe_is_i64(const void* buf, long long lo,
                                             long long hi, int* s_bad) {
    if (threadIdx.x == 0) *s_bad = 0;
    __syncthreads();
    if (threadIdx.x < 64) {
        long long v = ((const long long*)buf)[threadIdx.x];
        if (v < lo || v >= hi) atomicOr(s_bad, 1);
    }
    __syncthreads();
    return (*s_bad == 0);
}

// ---------------------------------------------------------------------------
// Stage 1: collapse face->vertex indirection into the padded L2 table.
// Only batch 0 of verts_attr matters (reference's replicated indexing bug:
// pix_to_face carries no per-batch offset, and batch 0's offset is zero).
// ---------------------------------------------------------------------------
__global__ __launch_bounds__(256) void uvr_build_face_table(
        const float* __restrict__ verts,
        const void*  __restrict__ faces) {
    __shared__ int s_bad;
    bool i64 = probe_is_i64(faces, 0, NUM_VERTS, &s_bad);

    int i = blockIdx.x * blockDim.x + threadIdx.x;   // over F*3
    if (i >= NUM_FACES * 3) return;
    long long v = i64 ? ((const long long*)faces)[i]
                      : (long long)((const int*)faces)[i];
    int vi = (int)v;
    vi = (vi < 0) ? 0 : (vi >= NUM_VERTS ? NUM_VERTS - 1 : vi);  // safety clamp
    const float* p = verts + (size_t)vi * 3;
    int f = i / 3, k = i - f * 3;
    g_face_attr[f * 4 + k] = make_float4(p[0], p[1], p[2], 0.0f);
}

// ---------------------------------------------------------------------------
// Stage 2: interpolate + 16-way batch broadcast. 4 pixels/thread.
// Proven R12 structure: default cached loads, __stcs streaming stores.
// block=128 / grid=2048 for fine wave granularity (R12's 1024x256 left a
// ~full-block quantization tail at 6.9 blocks/SM).
// ---------------------------------------------------------------------------
__global__ __launch_bounds__(BLK) void uvr_render(
        const void*  __restrict__ pixv,   // (H, W) indices
        const float* __restrict__ bary,   // (H, W, 3) f32
        float*       __restrict__ out) {  // (N, H, W, 3) f32
    __shared__ int s_bad;
    bool pix_i64 = probe_is_i64(pixv, -1, NUM_FACES, &s_bad);

    int t  = blockIdx.x * BLK + threadIdx.x;
    int p0 = t * PXT;                     // 4 pixels per thread, exact cover

    long long pf[4];
    if (pix_i64) {
        longlong2 a = ((const longlong2*)pixv)[t * 2];
        longlong2 b = ((const longlong2*)pixv)[t * 2 + 1];
        pf[0] = a.x; pf[1] = a.y; pf[2] = b.x; pf[3] = b.y;
    } else {
        int4 a = ((const int4*)pixv)[t];
        pf[0] = a.x; pf[1] = a.y; pf[2] = a.z; pf[3] = a.w;
    }

    const float4* bv = reinterpret_cast<const float4*>(bary + (size_t)p0 * 3);
    float4 b0 = bv[0], b1 = bv[1], b2 = bv[2];
    float bc[4][3] = {
        {b0.x, b0.y, b0.z},
        {b0.w, b1.x, b1.y},
        {b1.z, b1.w, b2.x},
        {b2.y, b2.z, b2.w}
    };

    float r[4][3];
#pragma unroll
    for (int i = 0; i < 4; i++) {
        long long f = pf[i];
        float m = (f >= 0) ? 1.0f : 0.0f;
        int idx = (int)f;
        idx = (idx < 0) ? 0 : (idx >= NUM_FACES ? NUM_FACES - 1 : idx);  // clamp
        // 64-B padded record: all three loads in one 128-B line.
        float4 a0 = g_face_attr[idx * 4 + 0];
        float4 a1 = g_face_attr[idx * 4 + 1];
        float4 a2 = g_face_attr[idx * 4 + 2];
        r[i][0] = m * (bc[i][0] * a0.x + bc[i][1] * a1.x + bc[i][2] * a2.x);
        r[i][1] = m * (bc[i][0] * a0.y + bc[i][1] * a1.y + bc[i][2] * a2.y);
        r[i][2] = m * (bc[i][0] * a0.z + bc[i][1] * a1.z + bc[i][2] * a2.z);
    }

    // Pack 4 pixels * 3 comps = 12 floats into 3 float4 (48 contiguous bytes).
    float4 o0 = make_float4(r[0][0], r[0][1], r[0][2], r[1][0]);
    float4 o1 = make_float4(r[1][1], r[1][2], r[2][0], r[2][1]);
    float4 o2 = make_float4(r[2][2], r[3][0], r[3][1], r[3][2]);

    size_t base = (size_t)p0 * 3;
#pragma unroll
    for (int n = 0; n < NB; n++) {
        float4* op = reinterpret_cast<float4*>(out + (size_t)n * ((size_t)HW * 3) + base);
        __stcs(op + 0, o0);
        __stcs(op + 1, o1);
        __stcs(op + 2, o2);
    }
}

extern "C" void kernel_launch(void* const* d_in, const int* in_sizes, int n_in,
                              void* d_out, int out_size) {
    // Identify inputs by element count (pairwise distinct) — order-proof.
    const float* verts = nullptr;
    const void*  faces = nullptr;
    const void*  pix   = nullptr;
    const float* bary  = nullptr;
    for (int i = 0; i < n_in; i++) {
        switch (in_sizes[i]) {
            case SZ_VERTS: verts = (const float*)d_in[i]; break;
            case SZ_FACES: faces = d_in[i];               break;
            case SZ_PIX:   pix   = d_in[i];               break;
            case SZ_BARY:  bary  = (const float*)d_in[i]; break;
            default: break;
        }
    }
    if (!verts) verts = (const float*)d_in[0];
    if (!faces) faces = d_in[1];
    if (!pix)   pix   = d_in[2];
    if (!bary)  bary  = (const float*)d_in[3];

    float* out = (float*)d_out;
    (void)out_size;

    {
        int n = NUM_FACES * 3;
        uvr_build_face_table<<<(n + 255) / 256, 256>>>(verts, faces);
    }
    {
        uvr_render<<<GRID, BLK>>>(pix, bary, out);   // 2048 x 128
    }
}